// round 14
// baseline (speedup 1.0000x reference)
#include <cuda_runtime.h>

#define N_NODES 50000
#define N_EDGES 600000
#define H 128

// ---------------- scratch (device globals; no allocation allowed) ----------
__device__ float4 g_mean4[(size_t)N_NODES * H / 4]; // mean-aggregated features
__device__ float4 g_h14[(size_t)N_NODES * H / 4];   // layer-1 output
__device__ float4 g_h24[(size_t)N_NODES * H / 4];   // layer-2 output

// CSR scratch (rebuilt every call; graph identical across layers)
__device__ int g_deg[N_NODES];
__device__ int g_fill[N_NODES];
__device__ int g_row_start[N_NODES + 1];
__device__ int g_edge_src[N_EDGES];
__device__ int g_is64;                              // edge dtype flag

// ---------------- packed f32x2 helpers (sm_103a FFMA2 path) -----------------
__device__ __forceinline__ unsigned long long pack2(float lo, float hi) {
    unsigned long long r;
    asm("mov.b64 %0, {%1, %2};" : "=l"(r) : "f"(lo), "f"(hi));
    return r;
}
__device__ __forceinline__ void ffma2(unsigned long long& d,
                                      unsigned long long a,
                                      unsigned long long b) {
    asm("fma.rn.f32x2 %0, %1, %2, %3;" : "=l"(d) : "l"(a), "l"(b), "l"(d));
}
__device__ __forceinline__ float2 unpack2(unsigned long long v) {
    float2 f;
    asm("mov.b64 {%0, %1}, %2;" : "=f"(f.x), "=f"(f.y) : "l"(v));
    return f;
}

// ---------------- edge-index access (dtype-robust) ---------------------------
__global__ void detect_kernel(const int* __restrict__ ei32) {
    if (blockIdx.x == 0 && threadIdx.x == 0) {
        int is64 = 1;
        for (int i = 1; i < 64; i += 2)
            if (ei32[i] != 0) { is64 = 0; break; }
        g_is64 = is64;
    }
}

__device__ __forceinline__ int load_idx(const int* __restrict__ ei32,
                                        int is64, int elem) {
    int v = is64 ? ei32[(size_t)elem * 2] : ei32[elem];
    return ((unsigned)v < (unsigned)N_NODES) ? v : 0;   // safety mask
}

// ---------------- CSR build --------------------------------------------------
__global__ void zero_csr_kernel() {
    int i = blockIdx.x * blockDim.x + threadIdx.x;
    if (i < N_NODES) { g_deg[i] = 0; g_fill[i] = 0; }
}

__global__ void hist_kernel(const int* __restrict__ ei32) {
    int e = blockIdx.x * blockDim.x + threadIdx.x;
    if (e >= N_EDGES) return;
    int is64 = g_is64;
    int dst = load_idx(ei32, is64, N_EDGES + e);
    atomicAdd(&g_deg[dst], 1);
}

// single-block parallel exclusive scan: per-thread chunk sums, warp-shuffle
// scan of 1024 partials (two levels), then per-thread serial writeback.
__global__ __launch_bounds__(1024)
void scan_kernel() {
    __shared__ int wsum[32];
    const int CH = (N_NODES + 1023) / 1024;   // 49
    int t = threadIdx.x;
    int lane = t & 31;
    int wid  = t >> 5;
    int base = t * CH;

    int s = 0;
#pragma unroll 7
    for (int i = 0; i < CH; i++) {
        int idx = base + i;
        if (idx < N_NODES) s += g_deg[idx];
    }
    // inclusive warp scan of per-thread sums
    int v = s;
#pragma unroll
    for (int d = 1; d < 32; d <<= 1) {
        int n = __shfl_up_sync(0xffffffffu, v, d);
        if (lane >= d) v += n;
    }
    if (lane == 31) wsum[wid] = v;
    __syncthreads();
    if (wid == 0) {
        int w = wsum[lane];
#pragma unroll
        for (int d = 1; d < 32; d <<= 1) {
            int n = __shfl_up_sync(0xffffffffu, w, d);
            if (lane >= d) w += n;
        }
        wsum[lane] = w;
    }
    __syncthreads();
    int run = (v - s) + (wid > 0 ? wsum[wid - 1] : 0);  // exclusive prefix
#pragma unroll 7
    for (int i = 0; i < CH; i++) {
        int idx = base + i;
        if (idx < N_NODES) { g_row_start[idx] = run; run += g_deg[idx]; }
    }
    if (t == 0) g_row_start[N_NODES] = N_EDGES;
}

__global__ void fill_kernel(const int* __restrict__ ei32) {
    int e = blockIdx.x * blockDim.x + threadIdx.x;
    if (e >= N_EDGES) return;
    int is64 = g_is64;
    int dst = load_idx(ei32, is64, N_EDGES + e);
    int src = load_idx(ei32, is64, e);
    int pos = g_row_start[dst] + atomicAdd(&g_fill[dst], 1);
    g_edge_src[pos] = src;
}

// ---------------- input selection (device-side; no host symbol APIs) --------
__device__ __forceinline__ const float4* sel_in4(int s, const float4* x4) {
    return (s == 0) ? x4 : (s == 1) ? g_h14 : g_h24;
}
__device__ __forceinline__ float* sel_out(int s, float* o) {
    return (s == 1) ? (float*)g_h14 : (s == 2) ? (float*)g_h24 : o;
}

// ---------------- gather: mean[n] = (1/max(deg,1)) * sum_{src in N(n)} h[src]
__global__ __launch_bounds__(256)
void gather_mean_kernel(const float* __restrict__ x, int in_sel) {
    int node = blockIdx.x * (blockDim.x >> 5) + (threadIdx.x >> 5);
    int lane = threadIdx.x & 31;
    if (node >= N_NODES) return;

    const float4* __restrict__ h4 = sel_in4(in_sel, (const float4*)x);

    int s = g_row_start[node];
    int e = g_row_start[node + 1];

    float4 acc0 = make_float4(0.f, 0.f, 0.f, 0.f);
    float4 acc1 = make_float4(0.f, 0.f, 0.f, 0.f);
    int i = s;
    for (; i + 1 < e; i += 2) {                 // 2-way MLP
        int s0 = g_edge_src[i];
        int s1 = g_edge_src[i + 1];
        float4 v0 = h4[(size_t)s0 * (H / 4) + lane];
        float4 v1 = h4[(size_t)s1 * (H / 4) + lane];
        acc0.x += v0.x; acc0.y += v0.y; acc0.z += v0.z; acc0.w += v0.w;
        acc1.x += v1.x; acc1.y += v1.y; acc1.z += v1.z; acc1.w += v1.w;
    }
    if (i < e) {
        int s0 = g_edge_src[i];
        float4 v0 = h4[(size_t)s0 * (H / 4) + lane];
        acc0.x += v0.x; acc0.y += v0.y; acc0.z += v0.z; acc0.w += v0.w;
    }
    float inv = 1.0f / fmaxf((float)(e - s), 1.0f);
    float4 m;
    m.x = (acc0.x + acc1.x) * inv;
    m.y = (acc0.y + acc1.y) * inv;
    m.z = (acc0.z + acc1.z) * inv;
    m.w = (acc0.w + acc1.w) * inv;
    g_mean4[(size_t)node * (H / 4) + lane] = m;
}

// ---------------- fused SAGE GEMM (FFMA2 / f32x2 packed math) ----------------
// out[i][j] = sum_k mean[i][k]*Wl[j][k] + sum_k h[i][k]*Wr[j][k] + b[j]
// One K=256 GEMM: A=[mean | h], B=[Wl ; Wr].
// B tile stored in shared PRE-PACKED as f32x2 pairs: pair p <-> columns
// (jA, jB) = ((p&15) + 32*(p>>4), jA+16). Inner loop: 16 fma.rn.f32x2
// per thread-k instead of 32 FFMA -> halves fma-pipe issue.
#define TM 64
#define KC 32
#define KPAD (KC + 4)

__global__ __launch_bounds__(256)
void sage_gemm_kernel(const float* __restrict__ x,
                      const float* __restrict__ Wl,
                      const float* __restrict__ Wr,
                      const float* __restrict__ bias,
                      float* __restrict__ dout,
                      int in_sel, int out_sel, int relu) {
    __shared__ float As[TM][KPAD];
    __shared__ unsigned long long Bp[KC][64];   // packed column pairs

    const float4* __restrict__ hin4 = sel_in4(in_sel, (const float4*)x);
    float* __restrict__ out         = sel_out(out_sel, dout);

    int tx = threadIdx.x & 15;
    int ty = threadIdx.x >> 4;
    int node0 = blockIdx.x * TM;

    // acc2[m][u2] covers columns (tx + 32*u2, tx + 32*u2 + 16)
    unsigned long long acc2[4][4];
#pragma unroll
    for (int u2 = 0; u2 < 4; u2++) {
        unsigned long long bj = pack2(bias[tx + 32 * u2], bias[tx + 32 * u2 + 16]);
#pragma unroll
        for (int m = 0; m < 4; m++) acc2[m][u2] = bj;
    }

    for (int kc = 0; kc < 256 / KC; kc++) {
        int kg0 = kc * KC;

        // A tile: 64 rows x KC cols (mean for kg<128, h for kg>=128)
#pragma unroll
        for (int r = 0; r < (TM * KC / 4) / 256; r++) {
            int idx = threadIdx.x + r * 256;       // float4 index
            int i   = idx >> 3;                    // KC/4 = 8 f4 per row
            int kv  = idx & 7;
            int gi  = node0 + i;
            int kg  = kg0 + kv * 4;
            float4 v = make_float4(0.f, 0.f, 0.f, 0.f);
            if (gi < N_NODES) {
                if (kg < H)
                    v = g_mean4[(size_t)gi * (H / 4) + (kg >> 2)];
                else
                    v = hin4[(size_t)gi * (H / 4) + ((kg - H) >> 2)];
            }
            *(float4*)&As[i][kv * 4] = v;
        }
        // B tile: 512 tasks = 64 pairs x 8 k-groups; pack column pairs
#pragma unroll
        for (int r = 0; r < 2; r++) {
            int idx = threadIdx.x + r * 256;
            int p   = idx & 63;
            int kv  = idx >> 6;
            int kg  = kg0 + kv * 4;
            const float* W = (kg < H) ? Wl : Wr;
            int kk = (kg < H) ? kg : (kg - H);
            int jA = (p & 15) + 32 * (p >> 4);
            int jB = jA + 16;
            float4 vA = ((const float4*)(W + (size_t)jA * H))[kk >> 2];
            float4 vB = ((const float4*)(W + (size_t)jB * H))[kk >> 2];
            Bp[kv * 4 + 0][p] = pack2(vA.x, vB.x);
            Bp[kv * 4 + 1][p] = pack2(vA.y, vB.y);
            Bp[kv * 4 + 2][p] = pack2(vA.z, vB.z);
            Bp[kv * 4 + 3][p] = pack2(vA.w, vB.w);
        }
        __syncthreads();

#pragma unroll
        for (int k = 0; k < KC; k++) {
            unsigned long long a2[4], b2[4];
#pragma unroll
            for (int m = 0; m < 4; m++) {
                float a = As[ty * 4 + m][k];
                a2[m] = pack2(a, a);
            }
#pragma unroll
            for (int u2 = 0; u2 < 4; u2++)
                b2[u2] = Bp[k][tx + 16 * u2];
#pragma unroll
            for (int m = 0; m < 4; m++)
#pragma unroll
                for (int u2 = 0; u2 < 4; u2++)
                    ffma2(acc2[m][u2], a2[m], b2[u2]);
        }
        __syncthreads();
    }

#pragma unroll
    for (int m = 0; m < 4; m++) {
        int gi = node0 + ty * 4 + m;
        if (gi < N_NODES) {
#pragma unroll
            for (int u2 = 0; u2 < 4; u2++) {
                float2 f = unpack2(acc2[m][u2]);
                if (relu) { f.x = fmaxf(f.x, 0.f); f.y = fmaxf(f.y, 0.f); }
                out[(size_t)gi * H + tx + 32 * u2]      = f.x;
                out[(size_t)gi * H + tx + 32 * u2 + 16] = f.y;
            }
        }
    }
}

// ---------------- launcher ---------------------------------------------------
extern "C" void kernel_launch(void* const* d_in, const int* in_sizes, int n_in,
                              void* d_out, int out_size) {
    const float* x    = (const float*)d_in[0];
    const int*   ei32 = (const int*)d_in[1];   // dtype auto-detected on device
    const float* Wl1 = (const float*)d_in[2];
    const float* Wr1 = (const float*)d_in[3];
    const float* b1  = (const float*)d_in[4];
    const float* Wl2 = (const float*)d_in[5];
    const float* Wr2 = (const float*)d_in[6];
    const float* b2  = (const float*)d_in[7];
    const float* Wl3 = (const float*)d_in[8];
    const float* Wr3 = (const float*)d_in[9];
    const float* b3  = (const float*)d_in[10];
    float* out = (float*)d_out;

    const int NODE_BLKS  = (N_NODES + 255) / 256;        // 196
    const int EDGE_BLKS  = (N_EDGES + 255) / 256;        // 2344
    const int GATH_BLKS  = (N_NODES + 7) / 8;            // 6250 (8 warps/block)
    const int GEMM_BLKS  = (N_NODES + TM - 1) / TM;      // 782

    // ---- CSR build (once; graph identical for all 3 layers) ----
    detect_kernel<<<1, 32>>>(ei32);
    zero_csr_kernel<<<NODE_BLKS, 256>>>();
    hist_kernel<<<EDGE_BLKS, 256>>>(ei32);
    scan_kernel<<<1, 1024>>>();
    fill_kernel<<<EDGE_BLKS, 256>>>(ei32);

    // ---- layer 1 (relu) ----
    gather_mean_kernel<<<GATH_BLKS, 256>>>(x, /*in_sel=*/0);
    sage_gemm_kernel<<<GEMM_BLKS, 256>>>(x, Wl1, Wr1, b1, out,
                                         /*in=*/0, /*out=*/1, /*relu=*/1);
    // ---- layer 2 ----
    gather_mean_kernel<<<GATH_BLKS, 256>>>(x, /*in_sel=*/1);
    sage_gemm_kernel<<<GEMM_BLKS, 256>>>(x, Wl2, Wr2, b2, out,
                                         /*in=*/1, /*out=*/2, /*relu=*/0);
    // ---- layer 3 (writes d_out) ----
    gather_mean_kernel<<<GATH_BLKS, 256>>>(x, /*in_sel=*/2);
    sage_gemm_kernel<<<GEMM_BLKS, 256>>>(x, Wl3, Wr3, b3, out,
                                         /*in=*/2, /*out=*/0, /*relu=*/0);
}

// round 16
// speedup vs baseline: 1.1028x; 1.1028x over previous
#include <cuda_runtime.h>

#define N_NODES 50000
#define N_EDGES 600000
#define H 128

// ---------------- scratch (device globals; no allocation allowed) ----------
__device__ float4 g_mean4[(size_t)N_NODES * H / 4]; // mean-aggregated features
__device__ float4 g_h14[(size_t)N_NODES * H / 4];   // layer-1 output
__device__ float4 g_h24[(size_t)N_NODES * H / 4];   // layer-2 output

// CSR scratch (rebuilt every call; graph identical across layers)
#define SCAN_BLOCKS ((N_NODES + 255) / 256)          // 196
__device__ int g_deg[N_NODES];
__device__ int g_fill[N_NODES];
__device__ int g_row_start[N_NODES + 1];
__device__ int g_edge_src[N_EDGES];
__device__ int g_blk[SCAN_BLOCKS];                   // per-block degree sums
__device__ int g_blkoff[SCAN_BLOCKS];                // exclusive block offsets
__device__ int g_is64;                               // edge dtype flag

// ---------------- edge-index access (dtype-robust) ---------------------------
__global__ void detect_kernel(const int* __restrict__ ei32) {
    if (blockIdx.x == 0 && threadIdx.x == 0) {
        int is64 = 1;
        for (int i = 1; i < 64; i += 2)
            if (ei32[i] != 0) { is64 = 0; break; }
        g_is64 = is64;
    }
}

__device__ __forceinline__ int load_idx(const int* __restrict__ ei32,
                                        int is64, int elem) {
    int v = is64 ? ei32[(size_t)elem * 2] : ei32[elem];
    return ((unsigned)v < (unsigned)N_NODES) ? v : 0;   // safety mask
}

// ---------------- CSR build --------------------------------------------------
__global__ void zero_csr_kernel() {
    int i = blockIdx.x * blockDim.x + threadIdx.x;
    if (i < N_NODES) { g_deg[i] = 0; g_fill[i] = 0; }
}

__global__ void hist_kernel(const int* __restrict__ ei32) {
    int e = blockIdx.x * blockDim.x + threadIdx.x;
    if (e >= N_EDGES) return;
    int is64 = g_is64;
    int dst = load_idx(ei32, is64, N_EDGES + e);
    atomicAdd(&g_deg[dst], 1);
}

// ---- 3-phase coalesced exclusive scan over degrees ----
// phase 1: per-block sums (coalesced)
__global__ __launch_bounds__(256)
void scan_blocksum_kernel() {
    __shared__ int wsum[8];
    int i = blockIdx.x * 256 + threadIdx.x;
    int lane = threadIdx.x & 31, wid = threadIdx.x >> 5;
    int v = (i < N_NODES) ? g_deg[i] : 0;
#pragma unroll
    for (int d = 16; d > 0; d >>= 1) v += __shfl_down_sync(0xffffffffu, v, d);
    if (lane == 0) wsum[wid] = v;
    __syncthreads();
    if (wid == 0) {
        int s = (lane < 8) ? wsum[lane] : 0;
#pragma unroll
        for (int d = 4; d > 0; d >>= 1) s += __shfl_down_sync(0xffffffffu, s, d);
        if (lane == 0) g_blk[blockIdx.x] = s;
    }
}

// phase 2: exclusive scan of 196 block sums (one block)
__global__ __launch_bounds__(256)
void scan_offsets_kernel() {
    __shared__ int wsum[8];
    int t = threadIdx.x;
    int lane = t & 31, wid = t >> 5;
    int s = (t < SCAN_BLOCKS) ? g_blk[t] : 0;
    int v = s;
#pragma unroll
    for (int d = 1; d < 32; d <<= 1) {
        int n = __shfl_up_sync(0xffffffffu, v, d);
        if (lane >= d) v += n;
    }
    if (lane == 31) wsum[wid] = v;
    __syncthreads();
    if (wid == 0) {
        int w = (lane < 8) ? wsum[lane] : 0;
#pragma unroll
        for (int d = 1; d < 8; d <<= 1) {
            int n = __shfl_up_sync(0xffffffffu, w, d);
            if (lane >= d) w += n;
        }
        if (lane < 8) wsum[lane] = w;
    }
    __syncthreads();
    int excl = (v - s) + (wid > 0 ? wsum[wid - 1] : 0);
    if (t < SCAN_BLOCKS) g_blkoff[t] = excl;
}

// phase 3: block-local exclusive scan + global offset (coalesced)
__global__ __launch_bounds__(256)
void scan_write_kernel() {
    __shared__ int wsum[8];
    int i = blockIdx.x * 256 + threadIdx.x;
    int lane = threadIdx.x & 31, wid = threadIdx.x >> 5;
    int s = (i < N_NODES) ? g_deg[i] : 0;
    int v = s;
#pragma unroll
    for (int d = 1; d < 32; d <<= 1) {
        int n = __shfl_up_sync(0xffffffffu, v, d);
        if (lane >= d) v += n;
    }
    if (lane == 31) wsum[wid] = v;
    __syncthreads();
    if (wid == 0) {
        int w = (lane < 8) ? wsum[lane] : 0;
#pragma unroll
        for (int d = 1; d < 8; d <<= 1) {
            int n = __shfl_up_sync(0xffffffffu, w, d);
            if (lane >= d) w += n;
        }
        if (lane < 8) wsum[lane] = w;
    }
    __syncthreads();
    int excl = (v - s) + (wid > 0 ? wsum[wid - 1] : 0) + g_blkoff[blockIdx.x];
    if (i < N_NODES) g_row_start[i] = excl;
    if (i == N_NODES - 1) g_row_start[N_NODES] = N_EDGES;
}

__global__ void fill_kernel(const int* __restrict__ ei32) {
    int e = blockIdx.x * blockDim.x + threadIdx.x;
    if (e >= N_EDGES) return;
    int is64 = g_is64;
    int dst = load_idx(ei32, is64, N_EDGES + e);
    int src = load_idx(ei32, is64, e);
    int pos = g_row_start[dst] + atomicAdd(&g_fill[dst], 1);
    g_edge_src[pos] = src;
}

// ---------------- input selection (device-side; no host symbol APIs) --------
__device__ __forceinline__ const float4* sel_in4(int s, const float4* x4) {
    return (s == 0) ? x4 : (s == 1) ? g_h14 : g_h24;
}
__device__ __forceinline__ float* sel_out(int s, float* o) {
    return (s == 1) ? (float*)g_h14 : (s == 2) ? (float*)g_h24 : o;
}

// ---------------- gather: mean[n] = (1/max(deg,1)) * sum_{src in N(n)} h[src]
__global__ __launch_bounds__(256)
void gather_mean_kernel(const float* __restrict__ x, int in_sel) {
    int node = blockIdx.x * (blockDim.x >> 5) + (threadIdx.x >> 5);
    int lane = threadIdx.x & 31;
    if (node >= N_NODES) return;

    const float4* __restrict__ h4 = sel_in4(in_sel, (const float4*)x);

    int s = g_row_start[node];
    int e = g_row_start[node + 1];

    float4 acc0 = make_float4(0.f, 0.f, 0.f, 0.f);
    float4 acc1 = make_float4(0.f, 0.f, 0.f, 0.f);
    int i = s;
    for (; i + 1 < e; i += 2) {                 // 2-way MLP
        int s0 = g_edge_src[i];
        int s1 = g_edge_src[i + 1];
        float4 v0 = h4[(size_t)s0 * (H / 4) + lane];
        float4 v1 = h4[(size_t)s1 * (H / 4) + lane];
        acc0.x += v0.x; acc0.y += v0.y; acc0.z += v0.z; acc0.w += v0.w;
        acc1.x += v1.x; acc1.y += v1.y; acc1.z += v1.z; acc1.w += v1.w;
    }
    if (i < e) {
        int s0 = g_edge_src[i];
        float4 v0 = h4[(size_t)s0 * (H / 4) + lane];
        acc0.x += v0.x; acc0.y += v0.y; acc0.z += v0.z; acc0.w += v0.w;
    }
    float inv = 1.0f / fmaxf((float)(e - s), 1.0f);
    float4 m;
    m.x = (acc0.x + acc1.x) * inv;
    m.y = (acc0.y + acc1.y) * inv;
    m.z = (acc0.z + acc1.z) * inv;
    m.w = (acc0.w + acc1.w) * inv;
    g_mean4[(size_t)node * (H / 4) + lane] = m;
}

// ---------------- fused SAGE GEMM (scalar FFMA, 8x8 micro-tile) --------------
// out[i][j] = sum_k mean[i][k]*Wl[j][k] + sum_k h[i][k]*Wr[j][k] + b[j]
// One K=256 GEMM: A=[mean | h] (128 rows/block), B=[Wl ; Wr] (128 rows).
// 256 threads (16x16), micro-tile 8 nodes x 8 cols -> 16 LDS per 64 FFMA.
#define TM 128
#define KC 32
#define KPAD (KC + 4)   // stride 36: f4-store conflict-free, <=2-way LDS

__global__ __launch_bounds__(256)
void sage_gemm_kernel(const float* __restrict__ x,
                      const float* __restrict__ Wl,
                      const float* __restrict__ Wr,
                      const float* __restrict__ bias,
                      float* __restrict__ dout,
                      int in_sel, int out_sel, int relu) {
    __shared__ float As[TM][KPAD];
    __shared__ float Bs[H][KPAD];

    const float4* __restrict__ hin4 = sel_in4(in_sel, (const float4*)x);
    float* __restrict__ out         = sel_out(out_sel, dout);

    int tx = threadIdx.x & 15;
    int ty = threadIdx.x >> 4;
    int node0 = blockIdx.x * TM;

    float acc[8][8];
#pragma unroll
    for (int u = 0; u < 8; u++) {
        float bj = bias[tx + 16 * u];
#pragma unroll
        for (int m = 0; m < 8; m++) acc[m][u] = bj;
    }

    for (int kc = 0; kc < 256 / KC; kc++) {
        int kg0 = kc * KC;

        // A tile: 128 rows x KC cols (mean for kg<128, h for kg>=128)
#pragma unroll
        for (int r = 0; r < (TM * KC / 4) / 256; r++) {     // 4 iters
            int idx = threadIdx.x + r * 256;   // float4 index
            int i   = idx >> 3;                // KC/4 = 8 f4 per row
            int kv  = idx & 7;
            int gi  = node0 + i;
            int kg  = kg0 + kv * 4;
            float4 v = make_float4(0.f, 0.f, 0.f, 0.f);
            if (gi < N_NODES) {
                if (kg < H)
                    v = g_mean4[(size_t)gi * (H / 4) + (kg >> 2)];
                else
                    v = hin4[(size_t)gi * (H / 4) + ((kg - H) >> 2)];
            }
            *(float4*)&As[i][kv * 4] = v;
        }
        // B tile: 128 rows x KC cols (Wl for kg<128, Wr for kg>=128)
#pragma unroll
        for (int r = 0; r < (H * KC / 4) / 256; r++) {      // 4 iters
            int idx = threadIdx.x + r * 256;
            int j   = idx >> 3;
            int kv  = idx & 7;
            int kg  = kg0 + kv * 4;
            const float* W = (kg < H) ? Wl : Wr;
            int kk = (kg < H) ? kg : (kg - H);
            float4 v = ((const float4*)(W + (size_t)j * H))[kk >> 2];
            *(float4*)&Bs[j][kv * 4] = v;
        }
        __syncthreads();

#pragma unroll
        for (int k = 0; k < KC; k++) {
            float a[8], bb[8];
#pragma unroll
            for (int m = 0; m < 8; m++) a[m] = As[ty * 8 + m][k];
#pragma unroll
            for (int u = 0; u < 8; u++) bb[u] = Bs[tx + 16 * u][k];
#pragma unroll
            for (int m = 0; m < 8; m++)
#pragma unroll
                for (int u = 0; u < 8; u++)
                    acc[m][u] = fmaf(a[m], bb[u], acc[m][u]);
        }
        __syncthreads();
    }

#pragma unroll
    for (int m = 0; m < 8; m++) {
        int gi = node0 + ty * 8 + m;
        if (gi < N_NODES) {
#pragma unroll
            for (int u = 0; u < 8; u++) {
                float v = acc[m][u];
                if (relu) v = fmaxf(v, 0.0f);
                out[(size_t)gi * H + tx + 16 * u] = v;
            }
        }
    }
}

// ---------------- launcher ---------------------------------------------------
extern "C" void kernel_launch(void* const* d_in, const int* in_sizes, int n_in,
                              void* d_out, int out_size) {
    const float* x    = (const float*)d_in[0];
    const int*   ei32 = (const int*)d_in[1];   // dtype auto-detected on device
    const float* Wl1 = (const float*)d_in[2];
    const float* Wr1 = (const float*)d_in[3];
    const float* b1  = (const float*)d_in[4];
    const float* Wl2 = (const float*)d_in[5];
    const float* Wr2 = (const float*)d_in[6];
    const float* b2  = (const float*)d_in[7];
    const float* Wl3 = (const float*)d_in[8];
    const float* Wr3 = (const float*)d_in[9];
    const float* b3  = (const float*)d_in[10];
    float* out = (float*)d_out;

    const int NODE_BLKS  = (N_NODES + 255) / 256;        // 196
    const int EDGE_BLKS  = (N_EDGES + 255) / 256;        // 2344
    const int GATH_BLKS  = (N_NODES + 7) / 8;            // 6250 (8 warps/block)
    const int GEMM_BLKS  = (N_NODES + TM - 1) / TM;      // 391

    // ---- CSR build (once; graph identical for all 3 layers) ----
    detect_kernel<<<1, 32>>>(ei32);
    zero_csr_kernel<<<NODE_BLKS, 256>>>();
    hist_kernel<<<EDGE_BLKS, 256>>>(ei32);
    scan_blocksum_kernel<<<SCAN_BLOCKS, 256>>>();
    scan_offsets_kernel<<<1, 256>>>();
    scan_write_kernel<<<SCAN_BLOCKS, 256>>>();
    fill_kernel<<<EDGE_BLKS, 256>>>(ei32);

    // ---- layer 1 (relu) ----
    gather_mean_kernel<<<GATH_BLKS, 256>>>(x, /*in_sel=*/0);
    sage_gemm_kernel<<<GEMM_BLKS, 256>>>(x, Wl1, Wr1, b1, out,
                                         /*in=*/0, /*out=*/1, /*relu=*/1);
    // ---- layer 2 ----
    gather_mean_kernel<<<GATH_BLKS, 256>>>(x, /*in_sel=*/1);
    sage_gemm_kernel<<<GEMM_BLKS, 256>>>(x, Wl2, Wr2, b2, out,
                                         /*in=*/1, /*out=*/2, /*relu=*/0);
    // ---- layer 3 (writes d_out) ----
    gather_mean_kernel<<<GATH_BLKS, 256>>>(x, /*in_sel=*/2);
    sage_gemm_kernel<<<GEMM_BLKS, 256>>>(x, Wl3, Wr3, b3, out,
                                         /*in=*/2, /*out=*/0, /*relu=*/0);
}